// round 17
// baseline (speedup 1.0000x reference)
#include <cuda_runtime.h>
#include <math.h>

#define B 32
#define S 4096
#define H 1024
#define WARPS_PER_BLOCK 8
#define THREADS (WARPS_PER_BLOCK * 32)      // 256
#define NBLOCKS 296                          // 2 blocks/SM on 148 SMs
#define NWARPS (NBLOCKS * WARPS_PER_BLOCK)   // 2368
#define WPB 74                               // warps per batch
#define ROWS_BASE 55
#define ROWS_REM 26                          // first 26 slots get 56 rows
#define MAX_SLOTS 11                         // max blocks spanning one batch

// Scratch (__device__ globals; no dynamic allocation allowed)
__device__ float4 g_ctx_partial[B * MAX_SLOTS * (H / 4)];   // 1.4 MB
__device__ float  g_m_partial[B * MAX_SLOTS];
__device__ float  g_l_partial[B * MAX_SLOTS];
__device__ unsigned int g_cnt[B];    // per-batch arrival counters (epoch via %nblk)

__device__ __forceinline__ int first_block_of(int b) { return (WPB * b) / WARPS_PER_BLOCK; }
__device__ __forceinline__ int nblk_of(int b) {
    return (WPB * b + WPB - 1) / WARPS_PER_BLOCK - (WPB * b) / WARPS_PER_BLOCK + 1;
}

// ---------------------------------------------------------------------------
// Single kernel, 296 blocks (full 2368-warp streaming).
// Warp wg serves batch wg/74 (blocks may span 2 batches).
// Phase 1: proven streaming body + coalesced score stores.
// Phase 1b: per-batch-group block combine (1-2 partials per block).
// Phase 2: last-arriving block of each batch finalizes it alone.
// ---------------------------------------------------------------------------
__global__ __launch_bounds__(THREADS, 2)
void attn_fused(const float* __restrict__ query,
                const float* __restrict__ keys,
                float* __restrict__ out_ctx,
                float* __restrict__ out_weights)
{
    const int w    = threadIdx.x >> 5;
    const int lane = threadIdx.x & 31;
    const int t    = threadIdx.x;
    const int wg   = blockIdx.x * WARPS_PER_BLOCK + w;
    const int b    = wg / WPB;
    const int i    = wg % WPB;
    const int start = i * ROWS_BASE + (i < ROWS_REM ? i : ROWS_REM);
    const int count = ROWS_BASE + (i < ROWS_REM ? 1 : 0);

    // block-level batch-group geometry
    const int b0     = (blockIdx.x * WARPS_PER_BLOCK) / WPB;
    const int wsplit = WPB * (b0 + 1) - blockIdx.x * WARPS_PER_BLOCK; // 1..74; >=8 => single group
    const int ngroups = (wsplit < WARPS_PER_BLOCK) ? 2 : 1;

    float m = -INFINITY;
    float l = 0.f;
    float4 acc[8];
#pragma unroll
    for (int j = 0; j < 8; ++j) acc[j] = make_float4(0.f, 0.f, 0.f, 0.f);

    // ======================== Phase 1: streaming ========================
    {
        const float4* q4 = reinterpret_cast<const float4*>(query + (size_t)b * H);
        float4 qv[8];
#pragma unroll
        for (int j = 0; j < 8; ++j) qv[j] = q4[lane + 32 * j];

        const size_t base = ((size_t)b * S + start) * H;
        float* wout = out_weights + (size_t)b * S + start;
        float sc = 0.f;                  // lane-selected score buffer

        for (int r = 0; r < count; ++r) {
            const float4* k4 = reinterpret_cast<const float4*>(keys + base + (size_t)r * H);
            float4 kv[8];
#pragma unroll
            for (int j = 0; j < 8; ++j) kv[j] = k4[lane + 32 * j];

            float d = 0.f;
#pragma unroll
            for (int j = 0; j < 8; ++j) {
                d = fmaf(qv[j].x, kv[j].x, d);
                d = fmaf(qv[j].y, kv[j].y, d);
                d = fmaf(qv[j].z, kv[j].z, d);
                d = fmaf(qv[j].w, kv[j].w, d);
            }
#pragma unroll
            for (int o = 16; o > 0; o >>= 1)
                d += __shfl_xor_sync(0xFFFFFFFFu, d, o);

            // coalesced score stores: one 128B line per 32 rows
            if ((r & 31) == lane) sc = d;
            if ((r & 31) == 31) wout[(r & ~31) + lane] = sc;

            float p;
            if (d > m) {                       // warp-uniform branch
                float scale = __expf(m - d);   // first iter: exp(-inf)=0
#pragma unroll
                for (int j = 0; j < 8; ++j) {
                    acc[j].x *= scale; acc[j].y *= scale;
                    acc[j].z *= scale; acc[j].w *= scale;
                }
                l = fmaf(l, scale, 1.f);
                m = d;
                p = 1.f;
            } else {
                p = __expf(d - m);
                l += p;
            }
#pragma unroll
            for (int j = 0; j < 8; ++j) {
                acc[j].x = fmaf(p, kv[j].x, acc[j].x);
                acc[j].y = fmaf(p, kv[j].y, acc[j].y);
                acc[j].z = fmaf(p, kv[j].z, acc[j].z);
                acc[j].w = fmaf(p, kv[j].w, acc[j].w);
            }
        }

        // flush score tail
        const int rem = count & 31;
        if (rem && lane < rem) wout[(count & ~31) + lane] = sc;
    }

    // ============ Phase 1b: per-group block combine ============
    __shared__ float  s_m[WARPS_PER_BLOCK], s_l[WARPS_PER_BLOCK];
    __shared__ float4 s_ctx[WARPS_PER_BLOCK][H / 4];   // 32 KB

    if (lane == 0) { s_m[w] = m; s_l[w] = l; }
#pragma unroll
    for (int j = 0; j < 8; ++j) s_ctx[w][lane + 32 * j] = acc[j];
    __syncthreads();

    // group maxima (all threads; 8 scalar smem reads)
    float gm0 = -INFINITY, gm1 = -INFINITY;
#pragma unroll
    for (int k = 0; k < WARPS_PER_BLOCK; ++k) {
        if (k < wsplit) gm0 = fmaxf(gm0, s_m[k]);
        else            gm1 = fmaxf(gm1, s_m[k]);
    }

    // per-thread combine: 8 row reads, two accumulators
    {
        float4 c0 = make_float4(0.f, 0.f, 0.f, 0.f);
        float4 c1 = make_float4(0.f, 0.f, 0.f, 0.f);
#pragma unroll
        for (int k = 0; k < WARPS_PER_BLOCK; ++k) {
            float4 v = s_ctx[k][t];
            if (k < wsplit) {
                const float f = __expf(s_m[k] - gm0);
                c0.x = fmaf(f, v.x, c0.x); c0.y = fmaf(f, v.y, c0.y);
                c0.z = fmaf(f, v.z, c0.z); c0.w = fmaf(f, v.w, c0.w);
            } else {
                const float f = __expf(s_m[k] - gm1);
                c1.x = fmaf(f, v.x, c1.x); c1.y = fmaf(f, v.y, c1.y);
                c1.z = fmaf(f, v.z, c1.z); c1.w = fmaf(f, v.w, c1.w);
            }
        }
        const int slot0 = blockIdx.x - first_block_of(b0);
        g_ctx_partial[(size_t)(b0 * MAX_SLOTS + slot0) * (H / 4) + t] = c0;
        if (ngroups == 2) {
            const int slot1 = blockIdx.x - first_block_of(b0 + 1);
            g_ctx_partial[(size_t)((b0 + 1) * MAX_SLOTS + slot1) * (H / 4) + t] = c1;
        }
        if (t == 0) {
            float gl0 = 0.f, gl1 = 0.f;
#pragma unroll
            for (int k = 0; k < WARPS_PER_BLOCK; ++k) {
                if (k < wsplit) gl0 += s_l[k] * __expf(s_m[k] - gm0);
                else            gl1 += s_l[k] * __expf(s_m[k] - gm1);
            }
            g_m_partial[b0 * MAX_SLOTS + slot0] = gm0;
            g_l_partial[b0 * MAX_SLOTS + slot0] = gl0;
            if (ngroups == 2) {
                const int slot1 = blockIdx.x - first_block_of(b0 + 1);
                g_m_partial[(b0 + 1) * MAX_SLOTS + slot1] = gm1;
                g_l_partial[(b0 + 1) * MAX_SLOTS + slot1] = gl1;
            }
        }
    }

    // =============== arrival: last block of each touched batch? ===============
    __shared__ unsigned int s_lastf[2];
    __threadfence();            // release: scores + partials (ALL threads fence)
    __syncthreads();
    if (t == 0) {
        for (int g = 0; g < 2; ++g) {
            if (g < ngroups) {
                const int bg = b0 + g;
                const unsigned int nb = (unsigned int)nblk_of(bg);
                unsigned int old = atomicAdd(&g_cnt[bg], 1u);
                s_lastf[g] = ((old % nb) == nb - 1u) ? 1u : 0u;
            } else s_lastf[g] = 0u;
        }
    }
    __syncthreads();
    if (!(s_lastf[0] | s_lastf[1])) return;
    __threadfence();            // acquire peers' partials + scores

    // ================== Phase 2: finalize owned batch(es) ==================
    __shared__ float sM, sInvL;
    __shared__ float sF[MAX_SLOTS];

    for (int g = 0; g < 2; ++g) {
        if (!s_lastf[g]) continue;          // uniform: flags in smem
        const int bg = b0 + g;
        const int nb = nblk_of(bg);

        if (t == 0) {
            float mv[MAX_SLOTS], lv[MAX_SLOTS];
            float M = -INFINITY;
            for (int k = 0; k < nb; ++k) {
                mv[k] = __ldcg(&g_m_partial[bg * MAX_SLOTS + k]);
                lv[k] = __ldcg(&g_l_partial[bg * MAX_SLOTS + k]);
                M = fmaxf(M, mv[k]);
            }
            float L = 0.f;
            for (int k = 0; k < nb; ++k) L += lv[k] * __expf(mv[k] - M);
            const float invL = 1.f / L;
            sM = M; sInvL = invL;
            for (int k = 0; k < nb; ++k) sF[k] = __expf(mv[k] - M) * invL;
        }
        __syncthreads();
        const float M = sM, invL = sInvL;

        // normalize weights of batch bg: 1024 float4, 4 per thread
        {
            float4* wv = reinterpret_cast<float4*>(out_weights + (size_t)bg * S);
#pragma unroll
            for (int k = 0; k < 4; ++k) {
                const int idx = t + 256 * k;
                float4 s = __ldcg(&wv[idx]);
                s.x = __expf(s.x - M) * invL;
                s.y = __expf(s.y - M) * invL;
                s.z = __expf(s.z - M) * invL;
                s.w = __expf(s.w - M) * invL;
                wv[idx] = s;
            }
        }

        // combine context: thread t owns float4 element t; <=11 independent loads
        {
            const size_t pbase = (size_t)bg * MAX_SLOTS * (H / 4) + t;
            float4 c = make_float4(0.f, 0.f, 0.f, 0.f);
#pragma unroll
            for (int k = 0; k < MAX_SLOTS; ++k) {
                if (k < nb) {
                    float4 v = __ldcg(&g_ctx_partial[pbase + (size_t)k * (H / 4)]);
                    const float f = sF[k];
                    c.x = fmaf(f, v.x, c.x);
                    c.y = fmaf(f, v.y, c.y);
                    c.z = fmaf(f, v.z, c.z);
                    c.w = fmaf(f, v.w, c.w);
                }
            }
            reinterpret_cast<float4*>(out_ctx)[bg * (H / 4) + t] = c;
        }
        __syncthreads();    // smem (sF/sM) reuse safety for second group
    }
}

extern "C" void kernel_launch(void* const* d_in, const int* in_sizes, int n_in,
                              void* d_out, int out_size)
{
    const float* query = (const float*)d_in[0];   // (32,1,1024)
    const float* keys  = (const float*)d_in[1];   // (32,4096,1024)
    float* out = (float*)d_out;
    float* out_ctx = out;                  // (B,H)
    float* out_w   = out + (size_t)B * H;  // (B,S)

    attn_fused<<<NBLOCKS, THREADS>>>(query, keys, out_ctx, out_w);
}